// round 15
// baseline (speedup 1.0000x reference)
#include <cuda_runtime.h>
#include <cuda_bf16.h>

constexpr int B_ROWS  = 1024;
constexpr int L_COLS  = 4096;
constexpr int THREADS = 256;               // threads per row-block
constexpr int PER     = L_COLS / THREADS;  // 16 elements per thread
// A2 = (2/tau) * log2(e): tau and base-2 conversion folded into one constant
constexpr float A2  = (2.0f / 0.85f) * 1.4426950408889634f;
constexpr float LN2 = 0.6931471805599453f;

// digest: per (row, thread-chunk): bits<<16 | exclusive_count   (1 MB)
__device__ unsigned g_aux[B_ROWS * THREADS];
__device__ float    g_T[B_ROWS];
__device__ float    g_row[B_ROWS];
__device__ unsigned g_counter;   // zero-init; self-resetting

__device__ __forceinline__ float f_ex2(float x) {
    float y; asm("ex2.approx.f32 %0, %1;" : "=f"(y) : "f"(x)); return y;
}
__device__ __forceinline__ float f_lg2(float x) {
    float y; asm("lg2.approx.f32 %0, %1;" : "=f"(y) : "f"(x)); return y;
}

// ---------------- Kernel A: label scan -> digest (all barriers live here) ----
__global__ __launch_bounds__(THREADS)
void divloss_scan_kernel(const int* __restrict__ lab_in) {
    const int row  = blockIdx.x;
    const int t    = threadIdx.x;
    const int lane = t & 31;
    const int warp = t >> 5;

    const int4* lab = reinterpret_cast<const int4*>(lab_in + (size_t)row * L_COLS) + t * 4;
    int4 l0 = __ldcs(lab + 0), l1 = __ldcs(lab + 1),
         l2 = __ldcs(lab + 2), l3 = __ldcs(lab + 3);

    unsigned bits =
         (unsigned)l0.x        | ((unsigned)l0.y << 1)  | ((unsigned)l0.z << 2)  | ((unsigned)l0.w << 3)
      | ((unsigned)l1.x << 4)  | ((unsigned)l1.y << 5)  | ((unsigned)l1.z << 6)  | ((unsigned)l1.w << 7)
      | ((unsigned)l2.x << 8)  | ((unsigned)l2.y << 9)  | ((unsigned)l2.z << 10) | ((unsigned)l2.w << 11)
      | ((unsigned)l3.x << 12) | ((unsigned)l3.y << 13) | ((unsigned)l3.z << 14) | ((unsigned)l3.w << 15);
    const int local = __popc(bits);

    int x = local;
#pragma unroll
    for (int o = 1; o < 32; o <<= 1) {
        int y = __shfl_up_sync(0xffffffffu, x, o);
        if (lane >= o) x += y;
    }
    __shared__ int s_warp[8];
    if (lane == 31) s_warp[warp] = x;
    __syncthreads();

    int off = 0, tot = 0;
#pragma unroll
    for (int w = 0; w < 8; ++w) {
        int s = s_warp[w];
        tot += s;
        if (w < warp) off += s;
    }

    const unsigned c0 = (unsigned)(off + (x - local));   // exclusive count, <= 4096
    g_aux[row * THREADS + t] = (bits << 16) | c0;
    if (t == 0) g_T[row] = (float)tot;
}

// ---------------- Kernel B: barrier-free softmax-KL sweep ------------------
__global__ __launch_bounds__(THREADS)
void divloss_main_kernel(const float* __restrict__ p_in,
                         float*       __restrict__ out) {
    const int row  = blockIdx.x;
    const int t    = threadIdx.x;
    const int lane = t & 31;
    const int warp = t >> 5;

    // two scalar loads replace the whole scan+barrier
    const unsigned aux = g_aux[row * THREADS + t];
    const float    Tf  = g_T[row];                 // L2-broadcast

    const float4* pv = reinterpret_cast<const float4*>(p_in + (size_t)row * L_COLS) + t * 4;
    float4 p0 = __ldcs(pv + 0), p1 = __ldcs(pv + 1),
           p2 = __ldcs(pv + 2), p3 = __ldcs(pv + 3);

    const unsigned bits = aux >> 16;
    float A2c = A2 * (float)(aux & 0xFFFFu);       // A2 * exclusive count
    const float d0f = (float)(t * PER + 1) + Tf;   // first denominator

    float pc[PER] = { p0.x, p0.y, p0.z, p0.w, p1.x, p1.y, p1.z, p1.w,
                      p2.x, p2.y, p2.z, p2.w, p3.x, p3.y, p3.z, p3.w };

    float s1 = 0.0f, s2 = 0.0f;
    if (d0f >= 1024.0f) {
        // one RCP per 8-element chunk; 1/(dc+j) = invc*(1 - x + x^2)
#pragma unroll
        for (int c = 0; c < 2; ++c) {
            const float dc   = d0f + (float)(8 * c);
            const float invc = __frcp_rn(dc) ;     // exact rcp once per chunk
#pragma unroll
            for (int j = 0; j < 8; ++j) {
                int bj = (int)((bits >> (8 * c + j)) & 1u);
                A2c += __int_as_float(bj * 0x3F800000) * A2;   // IMAD + FFMA
                float xi   = (float)j * invc;
                float corr = fmaf(xi, xi, 1.0f) - xi;          // 1 - x + x^2
                float u    = (A2c * corr) * invc;              // r * log2e
                float e    = f_ex2(u);
                float gv   = f_lg2(pc[8 * c + j]);
                s1 += e;
                s2  = fmaf(e, u - gv, s2);
            }
        }
    } else {
        // rare small-T path: exact per-element divide
#pragma unroll
        for (int j = 0; j < PER; ++j) {
            int bj = (int)((bits >> j) & 1u);
            A2c += __int_as_float(bj * 0x3F800000) * A2;
            float u  = __fdividef(A2c, d0f + (float)j);
            float e  = f_ex2(u);
            float gv = f_lg2(pc[j]);
            s1 += e;
            s2  = fmaf(e, u - gv, s2);
        }
    }

    // ---- end-of-block reduce (the only barrier; absorbs skew) ----
#pragma unroll
    for (int o = 16; o; o >>= 1) {
        s1 += __shfl_down_sync(0xffffffffu, s1, o);
        s2 += __shfl_down_sync(0xffffffffu, s2, o);
    }
    __shared__ float r1[8], r2[8];
    if (lane == 0) { r1[warp] = s1; r2[warp] = s2; }
    __syncthreads();

    __shared__ bool s_last;
    if (t == 0) {
        float a1 = (r1[0] + r1[1]) + (r1[2] + r1[3])
                 + (r1[4] + r1[5]) + (r1[6] + r1[7]);
        float a2 = (r2[0] + r2[1]) + (r2[2] + r2[3])
                 + (r2[4] + r2[5]) + (r2[6] + r2[7]);
        // row = ln2 * (S2'/S1 - lg2(S1))
        g_row[row] = (__fdividef(a2, a1) - f_lg2(a1)) * LN2;
        __threadfence();
        unsigned done = atomicAdd(&g_counter, 1u);
        s_last = (done == (unsigned)(B_ROWS - 1));
    }
    __syncthreads();

    // ---- last block: deterministic final reduction of all 1024 rows ----
    if (s_last) {
        if (t == 0) g_counter = 0;   // reset for graph replay
        float v = (g_row[t] + g_row[t + 256]) + (g_row[t + 512] + g_row[t + 768]);
#pragma unroll
        for (int o = 16; o; o >>= 1) v += __shfl_down_sync(0xffffffffu, v, o);
        __shared__ float sh[8];
        if (lane == 0) sh[warp] = v;
        __syncthreads();
        if (t == 0) {
            float w = (sh[0] + sh[1]) + (sh[2] + sh[3])
                    + (sh[4] + sh[5]) + (sh[6] + sh[7]);
            out[0] = w * (1.0f / (float)B_ROWS);
        }
    }
}

extern "C" void kernel_launch(void* const* d_in, const int* in_sizes, int n_in,
                              void* d_out, int out_size) {
    const float* p_in   = (const float*)d_in[0];   // output: (B, L, 1) float32
    const int*   labels = (const int*)  d_in[1];   // labels: (B, L) int32
    float*       out    = (float*)d_out;

    divloss_scan_kernel<<<B_ROWS, THREADS>>>(labels);
    divloss_main_kernel<<<B_ROWS, THREADS>>>(p_in, out);
}